// round 16
// baseline (speedup 1.0000x reference)
#include <cuda_runtime.h>
#include <cuda_bf16.h>
#include <stdint.h>

// ---------------------------------------------------------------------------
// out[b,i,j] = (x_i - x_j)^T M_b (x_i - x_j) = q_i + q_j - 2*G[b,i,j]
//   G = x M_b x^T,  q_i = G_ii.   B=16, N=D=256, fp32.
// Split-bf16 (hi/lo) mma.sync GEMMs, fp32 accum. M symmetric => no transposes.
// R16: R15 but GEMMs use BK=64 (4 mainloop iterations instead of 8) —
//      32KB stages (128B rows, swizzle c^(row&7)), 3 stages, half the
//      barriers, double per-iteration independent work.
// ---------------------------------------------------------------------------

__device__ __align__(16) unsigned short g_Xh[256 * 256];
__device__ __align__(16) unsigned short g_Xl[256 * 256];
__device__ __align__(16) unsigned short g_Mh[16 * 256 * 256];
__device__ __align__(16) unsigned short g_Ml[16 * 256 * 256];
__device__ __align__(16) unsigned short g_Yh[16 * 256 * 256];
__device__ __align__(16) unsigned short g_Yl[16 * 256 * 256];
__device__ float g_q[16 * 256];

__device__ __forceinline__ uint32_t smem_u32(const void* p) {
    uint32_t a;
    asm("{ .reg .u64 t; cvta.to.shared.u64 t, %1; cvt.u32.u64 %0, t; }"
        : "=r"(a) : "l"(p));
    return a;
}

__device__ __forceinline__ void cp16(uint32_t dst, const void* src) {
    asm volatile("cp.async.cg.shared.global [%0], [%1], 16;"
                 :: "r"(dst), "l"(src) : "memory");
}
#define CP_COMMIT() asm volatile("cp.async.commit_group;" ::: "memory")
template <int N>
__device__ __forceinline__ void cp_wait() {
    asm volatile("cp.async.wait_group %0;" :: "n"(N) : "memory");
}

__device__ __forceinline__ void ldm_x4(uint32_t* r, uint32_t addr) {
    asm volatile("ldmatrix.sync.aligned.m8n8.x4.shared.b16 {%0,%1,%2,%3}, [%4];"
                 : "=r"(r[0]), "=r"(r[1]), "=r"(r[2]), "=r"(r[3]) : "r"(addr));
}
__device__ __forceinline__ void mma_bf16(float* d, const uint32_t* a,
                                         uint32_t b0, uint32_t b1) {
    asm volatile(
        "mma.sync.aligned.m16n8k16.row.col.f32.bf16.bf16.f32 "
        "{%0,%1,%2,%3}, {%4,%5,%6,%7}, {%8,%9}, {%0,%1,%2,%3};"
        : "+f"(d[0]), "+f"(d[1]), "+f"(d[2]), "+f"(d[3])
        : "r"(a[0]), "r"(a[1]), "r"(a[2]), "r"(a[3]), "r"(b0), "r"(b1));
}

__device__ __forceinline__ void split_pack(float v0, float v1,
                                           uint32_t& ph, uint32_t& pl) {
    const __nv_bfloat16 h0 = __float2bfloat16(v0);
    const __nv_bfloat16 h1 = __float2bfloat16(v1);
    const __nv_bfloat16 e0 = __float2bfloat16(v0 - __bfloat162float(h0));
    const __nv_bfloat16 e1 = __float2bfloat16(v1 - __bfloat162float(h1));
    ph = (uint32_t)__bfloat16_as_ushort(h0) | ((uint32_t)__bfloat16_as_ushort(h1) << 16);
    pl = (uint32_t)__bfloat16_as_ushort(e0) | ((uint32_t)__bfloat16_as_ushort(e1) << 16);
}

// ---------------------------------------------------------------------------
// Convert (R15): 8 floats/thread, 544 blocks x 256 threads; zeroes g_q.
// ---------------------------------------------------------------------------
__global__ void __launch_bounds__(256) k_convert(const float* __restrict__ x,
                                                 const float* __restrict__ M) {
    const int t = blockIdx.x * 256 + threadIdx.x;
    if (t < 16 * 256) g_q[t] = 0.0f;

    const float* src;
    unsigned short *dh, *dl;
    if (t < 131072) {           // M
        src = M + (size_t)t * 8;
        dh = g_Mh + t * 8;  dl = g_Ml + t * 8;
    } else {                    // x
        const int u = t - 131072;
        if (u >= 8192) return;
        src = x + (size_t)u * 8;
        dh = g_Xh + u * 8;  dl = g_Xl + u * 8;
    }

    const float4 a = ((const float4*)src)[0];
    const float4 c = ((const float4*)src)[1];
    uint32_t ph[4], pl[4];
    split_pack(a.x, a.y, ph[0], pl[0]);
    split_pack(a.z, a.w, ph[1], pl[1]);
    split_pack(c.x, c.y, ph[2], pl[2]);
    split_pack(c.z, c.w, ph[3], pl[3]);
    *(uint4*)dh = make_uint4(ph[0], ph[1], ph[2], ph[3]);
    *(uint4*)dl = make_uint4(pl[0], pl[1], pl[2], pl[3]);
}

// ---------------------------------------------------------------------------
// GEMM: block tile 64x64, 256 threads = 8 warps (2 m-warps x 4 n-warps),
// warp tile 32x16, BK=64, 3-stage cp.async pipeline (stage 32KB).
//   D += Ah*Bh + Ah*Bl + Al*Bh   (fp32 register accum)
// Stage: Ah@0 (64 rows x 128B), Al@8192, Bh@16384, Bl@24576.
// 16B-chunk swizzle c ^ (row & 7), rows are 128B = 8 chunks.
//   cp.async stores: thread covers chunks {c4, c4+4} of its row.
//   ldmatrix phase (8 rows, same logical chunk): row&7 takes all 8 values
//   => physical chunks distinct => conflict-free.
// PHASE 1: A=x, Bt=M_b rows; epilogue -> Yh/Yl + fused partial q (atomics).
// PHASE 2: A=Y_b, Bt=x rows; epilogue -> out = q_i + q_j - 2*acc.
// ---------------------------------------------------------------------------
#define STAGES  3
#define STAGE_B 32768
#define QS_OFF  (STAGES * STAGE_B)
#define SMEM_B  (QS_OFF + 1024)

template <int PHASE>
__global__ void __launch_bounds__(256) k_gemm(const float* __restrict__ x,
                                              float* __restrict__ out) {
    extern __shared__ __align__(128) unsigned char smem[];
    const uint32_t sb = smem_u32(smem);
    const int tid = threadIdx.x;
    const int wid = tid >> 5, l = tid & 31;
    const int wm  = wid & 1, wn = wid >> 1;      // 2 x 4 warp grid
    const int b   = blockIdx.z;
    const int bm0 = blockIdx.y * 64;
    const int bn0 = blockIdx.x * 64;

    const unsigned short *Ah, *Al, *Bh, *Bl;
    if (PHASE == 1) {
        Ah = g_Xh + bm0 * 256;             Al = g_Xl + bm0 * 256;
        Bh = g_Mh + b * 65536 + bn0 * 256; Bl = g_Ml + b * 65536 + bn0 * 256;
    } else {
        Ah = g_Yh + b * 65536 + bm0 * 256; Al = g_Yl + b * 65536 + bm0 * 256;
        Bh = g_Xh + bn0 * 256;             Bl = g_Xl + bn0 * 256;
    }

    if (PHASE == 2) {
        float* qs = (float*)(smem + QS_OFF);
        qs[tid] = g_q[b * 256 + tid];
    }

    // one BK=64 chunk (kc 0..3) into stage s: 8 cp16 per thread
    auto issue = [&](int kc, int s) {
        const uint32_t st = sb + s * STAGE_B;
        const int k0 = kc * 64;
        const int row = tid >> 2;
        const int c4 = tid & 3;
        #pragma unroll
        for (int h = 0; h < 2; h++) {
            const int c = c4 + h * 4;               // logical chunk 0..7
            const uint32_t d = st + row * 128 + ((c ^ (row & 7)) << 4);
            const int go = row * 256 + k0 + c * 8;
            cp16(d,         Ah + go);
            cp16(d + 8192,  Al + go);
            cp16(d + 16384, Bh + go);
            cp16(d + 24576, Bl + go);
        }
    };

    float acc[2][2][4] = {};   // [mt][n8 j][reg]

    issue(0, 0); CP_COMMIT();
    issue(1, 1); CP_COMMIT();

    const int rA = (l & 15);                    // A: row within m16 tile
    const int hA = (l >> 4);                    // A: k8-half select
    const int rB = ((l >> 4) << 3) + (l & 7);   // B: n-row within n16 group
    const int hB = ((l >> 3) & 1);              // B: k8-half select

    for (int i = 0; i < 4; i++) {
        if (i <= 1) cp_wait<1>();
        else        cp_wait<0>();
        __syncthreads();
        if (i + 2 < 4) { issue(i + 2, (i + 2) % 3); CP_COMMIT(); }

        const uint32_t st = sb + (i % 3) * STAGE_B;

        #pragma unroll
        for (int ks = 0; ks < 4; ks++) {        // 4 k16-steps per BK=64
            uint32_t ah[2][4], al[2][4], bh[4], bl[4];
            #pragma unroll
            for (int mt = 0; mt < 2; mt++) {
                const int row = wm * 32 + mt * 16 + rA;
                const int c = (ks * 2 + hA) ^ (row & 7);
                const uint32_t a = st + row * 128 + (c << 4);
                ldm_x4(ah[mt], a);
                ldm_x4(al[mt], a + 8192);
            }
            {
                const int row = wn * 16 + rB;
                const int c = (ks * 2 + hB) ^ (row & 7);
                const uint32_t a = st + 16384 + row * 128 + (c << 4);
                ldm_x4(bh, a);
                ldm_x4(bl, a + 8192);
            }
            #pragma unroll
            for (int mt = 0; mt < 2; mt++)
                #pragma unroll
                for (int j = 0; j < 2; j++) {
                    const int o = j * 2;
                    mma_bf16(acc[mt][j], ah[mt], bh[o], bh[o + 1]);
                    mma_bf16(acc[mt][j], ah[mt], bl[o], bl[o + 1]);
                    mma_bf16(acc[mt][j], al[mt], bh[o], bh[o + 1]);
                }
        }
    }

    // ------------------------------------------------------------------ epi
    const int lr = l >> 2;          // 0..7
    const int lc = (l & 3) * 2;     // 0,2,4,6

    if (PHASE == 1) {
        unsigned short* yh = g_Yh + b * 65536;
        unsigned short* yl = g_Yl + b * 65536;
        #pragma unroll
        for (int mt = 0; mt < 2; mt++)
            #pragma unroll
            for (int half = 0; half < 2; half++) {
                const int row = bm0 + wm * 32 + mt * 16 + lr + half * 8;
                float qpart = 0.0f;
                #pragma unroll
                for (int j = 0; j < 2; j++) {
                    const int col = bn0 + wn * 16 + j * 8 + lc;
                    const float v0 = acc[mt][j][half * 2 + 0];
                    const float v1 = acc[mt][j][half * 2 + 1];
                    const float2 xv = *(const float2*)(x + row * 256 + col);
                    qpart += v0 * xv.x + v1 * xv.y;
                    uint32_t ph, pl;
                    split_pack(v0, v1, ph, pl);
                    *(uint32_t*)(yh + row * 256 + col) = ph;
                    *(uint32_t*)(yl + row * 256 + col) = pl;
                }
                qpart += __shfl_xor_sync(0xffffffffu, qpart, 1);
                qpart += __shfl_xor_sync(0xffffffffu, qpart, 2);
                if ((l & 3) == 0) atomicAdd(g_q + b * 256 + row, qpart);
            }
    } else {
        const float* qs = (const float*)(smem + QS_OFF);
        float* ob = out + ((size_t)b << 16);
        #pragma unroll
        for (int mt = 0; mt < 2; mt++)
            #pragma unroll
            for (int j = 0; j < 2; j++) {
                const int col = bn0 + wn * 16 + j * 8 + lc;
                const float qj0 = qs[col], qj1 = qs[col + 1];
                #pragma unroll
                for (int half = 0; half < 2; half++) {
                    const int row = bm0 + wm * 32 + mt * 16 + lr + half * 8;
                    const float qi = qs[row];
                    float2 v;
                    v.x = qi + qj0 - 2.0f * acc[mt][j][half * 2 + 0];
                    v.y = qi + qj1 - 2.0f * acc[mt][j][half * 2 + 1];
                    *(float2*)(ob + row * 256 + col) = v;
                }
            }
    }
}

// ---------------------------------------------------------------------------
extern "C" void kernel_launch(void* const* d_in, const int* in_sizes, int n_in,
                              void* d_out, int out_size) {
    const float* x = (const float*)d_in[0];   // (256, 256) f32
    const float* M = (const float*)d_in[1];   // (16, 256, 256) f32
    float* out = (float*)d_out;               // (16, 256, 256) f32
    (void)in_sizes; (void)n_in; (void)out_size;

    (void)cudaFuncSetAttribute(k_gemm<1>, cudaFuncAttributeMaxDynamicSharedMemorySize, SMEM_B);
    (void)cudaFuncSetAttribute(k_gemm<2>, cudaFuncAttributeMaxDynamicSharedMemorySize, SMEM_B);

    k_convert<<<544, 256>>>(x, M);
    k_gemm<1><<<dim3(4, 4, 16), 256, SMEM_B>>>(x, nullptr);
    k_gemm<2><<<dim3(4, 4, 16), 256, SMEM_B>>>(x, out);
}